// round 12
// baseline (speedup 1.0000x reference)
#include <cuda_runtime.h>
#include <cuda_bf16.h>
#include <cstdint>

#define Sdim 2048
#define Bdim 2
#define Edim 1024
#define Hdim 16
#define Ddim 64
#define APAD 40   // bf16 elems per smem tile row (80B stride: conflict-free ldmatrix)
#define VPAD 72   // ctx V tile row pad (144B stride: conflict-free trans ldmatrix)
#define SP   132  // fp32 staging pad (proj/scores) — 528B row stride, 16B aligned
#define CP   68   // fp32 staging pad (ctx) — 272B row stride, 16B aligned

typedef uint32_t u32;

// scratch: static device arrays (allocation-free rule)
__device__ float g_Q[Bdim*Hdim*Sdim*Ddim];     // [B,H,S,D]
__device__ float g_K[Bdim*Hdim*Sdim*Ddim];     // [B,H,S,D]
__device__ float g_V[Bdim*Hdim*Sdim*Ddim];     // [B,H,S,D]
__device__ float g_ctx[Bdim*Sdim*Edim];        // [B,S,E]
__device__ float g_psum[Bdim*Hdim*Sdim*16];    // per-(row, ktile) exp partial sums
__device__ float g_inv[Bdim*Hdim*Sdim];        // 1/rowsum

__device__ __forceinline__ u32 smem_u32(const void* p){
    u32 a;
    asm("{ .reg .u64 t; cvta.to.shared.u64 t, %1; cvt.u32.u64 %0, t; }" : "=r"(a) : "l"(p));
    return a;
}
__device__ __forceinline__ void ldsm4(u32 r[4], u32 addr){
    asm volatile("ldmatrix.sync.aligned.m8n8.x4.shared.b16 {%0,%1,%2,%3}, [%4];"
        : "=r"(r[0]),"=r"(r[1]),"=r"(r[2]),"=r"(r[3]) : "r"(addr));
}
__device__ __forceinline__ void ldsm2t(u32 r[2], u32 addr){
    asm volatile("ldmatrix.sync.aligned.m8n8.x2.trans.shared.b16 {%0,%1}, [%2];"
        : "=r"(r[0]),"=r"(r[1]) : "r"(addr));
}
__device__ __forceinline__ void mma16816(float c[4], const u32 a[4], const u32 b[2]){
    asm volatile("mma.sync.aligned.m16n8k16.row.col.f32.bf16.bf16.f32 "
        "{%0,%1,%2,%3}, {%4,%5,%6,%7}, {%8,%9}, {%0,%1,%2,%3};"
        : "+f"(c[0]),"+f"(c[1]),"+f"(c[2]),"+f"(c[3])
        : "r"(a[0]),"r"(a[1]),"r"(a[2]),"r"(a[3]), "r"(b[0]),"r"(b[1]));
}

// 8 consecutive floats -> 16B hi-bf16 uint4 + 16B lo-bf16 uint4
__device__ __forceinline__ void split8(float4 a, float4 b, uint4& hi, uint4& lo){
    __nv_bfloat16 h0=__float2bfloat16(a.x), h1=__float2bfloat16(a.y),
                  h2=__float2bfloat16(a.z), h3=__float2bfloat16(a.w),
                  h4=__float2bfloat16(b.x), h5=__float2bfloat16(b.y),
                  h6=__float2bfloat16(b.z), h7=__float2bfloat16(b.w);
    __nv_bfloat162 p0=__halves2bfloat162(h0,h1), p1=__halves2bfloat162(h2,h3),
                   p2=__halves2bfloat162(h4,h5), p3=__halves2bfloat162(h6,h7);
    hi = make_uint4(*(u32*)&p0, *(u32*)&p1, *(u32*)&p2, *(u32*)&p3);
    __nv_bfloat162 q0=__floats2bfloat162_rn(a.x-__bfloat162float(h0), a.y-__bfloat162float(h1));
    __nv_bfloat162 q1=__floats2bfloat162_rn(a.z-__bfloat162float(h2), a.w-__bfloat162float(h3));
    __nv_bfloat162 q2=__floats2bfloat162_rn(b.x-__bfloat162float(h4), b.y-__bfloat162float(h5));
    __nv_bfloat162 q3=__floats2bfloat162_rn(b.z-__bfloat162float(h6), b.w-__bfloat162float(h7));
    lo = make_uint4(*(u32*)&q0, *(u32*)&q1, *(u32*)&q2, *(u32*)&q3);
}

#define PROJ_DSM (128*SP*4)
// ctx smem: bf16 tiles Ah/Al (64*APAD each) + Vh/Vl (32*VPAD each) = 19456B;
// fp32 staging 64*CP*4 = 17408B aliases the same region.
#define CTX_DSM  (2*(64*APAD*2) + 2*(32*VPAD*2))

// GEMM compute for one 16-wide K slab (4x2 warps, 8 nf), B pairs via ldsm4.
#define GEMM_COMPUTE_128(KS, sAh, sAl, sBh, sBl)                               \
    do {                                                                       \
        u32 ah0[4], ah1[4], al0[4], al1[4];                                    \
        u32 aoff0 = (sAh) + (u32)((wm      + a_r)*APAD + (KS) + a_c) * 2;      \
        u32 aoff1 = (sAh) + (u32)((wm + 16 + a_r)*APAD + (KS) + a_c) * 2;      \
        u32 loff0 = (sAl) + (u32)((wm      + a_r)*APAD + (KS) + a_c) * 2;      \
        u32 loff1 = (sAl) + (u32)((wm + 16 + a_r)*APAD + (KS) + a_c) * 2;      \
        ldsm4(ah0, aoff0); ldsm4(ah1, aoff1);                                  \
        ldsm4(al0, loff0); ldsm4(al1, loff1);                                  \
        _Pragma("unroll")                                                      \
        for (int nf = 0; nf < 8; nf += 2) {                                    \
            u32 bo = (u32)((wn + nf*8 + b_pn + b_pr)*APAD + (KS) + b_pc) * 2;  \
            u32 bh4[4], bl4[4];                                                \
            ldsm4(bh4, (sBh) + bo); ldsm4(bl4, (sBl) + bo);                    \
            mma16816(acc[nf],     ah0, bh4);                                   \
            mma16816(acc[nf],     ah0, bl4);                                   \
            mma16816(acc[nf],     al0, bh4);                                   \
            mma16816(acc[8+nf],   ah1, bh4);                                   \
            mma16816(acc[8+nf],   ah1, bl4);                                   \
            mma16816(acc[8+nf],   al1, bh4);                                   \
            mma16816(acc[nf+1],   ah0, bh4+2);                                 \
            mma16816(acc[nf+1],   ah0, bl4+2);                                 \
            mma16816(acc[nf+1],   al0, bh4+2);                                 \
            mma16816(acc[8+nf+1], ah1, bh4+2);                                 \
            mma16816(acc[8+nf+1], ah1, bl4+2);                                 \
            mma16816(acc[8+nf+1], al1, bh4+2);                                 \
        }                                                                      \
    } while (0)

// ---------------------------------------------------------------------------
// Shared projection core: out[m,f] = sum_e A[m,e]*W[f,e] + bias[f].
// modes 0/1/2: scatter to g_Q/g_K/g_V as [B,H,S,D]; 3: -> outp [S,B,E].
// ---------------------------------------------------------------------------
__device__ __forceinline__ void proj_core(
    const float* __restrict__ A, const float* __restrict__ W,
    const float* __restrict__ bias, float* __restrict__ outp, int mode, char* dsm)
{
    __nv_bfloat16* Ah = (__nv_bfloat16*)dsm;
    __nv_bfloat16* Al = Ah + 128*APAD;
    __nv_bfloat16* Bh = Al + 128*APAD;
    __nv_bfloat16* Bl = Bh + 128*APAD;
    float* stg = (float*)dsm;

    int tid = threadIdx.x, wid = tid >> 5, lane = tid & 31;
    int m0 = blockIdx.y << 7, f0 = blockIdx.x << 7;
    int wm = (wid & 3) << 5, wn = (wid >> 2) << 6;

    u32 sAh = smem_u32(Ah), sAl = smem_u32(Al), sBh = smem_u32(Bh), sBl = smem_u32(Bl);

    int a_r = (lane & 7) + ((lane >> 3) & 1) * 8;
    int a_c = ((lane >> 4) & 1) * 8;
    int b_pr = lane & 7;
    int b_pc = ((lane >> 3) & 1) * 8;
    int b_pn = (lane >> 4) * 8;

    int lr = tid >> 2, lc = (tid & 3) * 8;

    float acc[16][4];
    #pragma unroll
    for (int i = 0; i < 16; i++){ acc[i][0]=0.f; acc[i][1]=0.f; acc[i][2]=0.f; acc[i][3]=0.f; }

    const float* Ap  = A + (size_t)(m0 + lr)*Edim + lc;
    const float* Ap2 = Ap + (size_t)64*Edim;
    const float* Wp  = W + (size_t)(f0 + lr)*Edim + lc;
    const float* Wp2 = Wp + (size_t)64*Edim;

    for (int c = 0; c < 32; c++) {
        float4 a0 = *(const float4*)(Ap  + c*32), a1 = *(const float4*)(Ap  + c*32 + 4);
        float4 a2 = *(const float4*)(Ap2 + c*32), a3 = *(const float4*)(Ap2 + c*32 + 4);
        float4 w0 = *(const float4*)(Wp  + c*32), w1 = *(const float4*)(Wp  + c*32 + 4);
        float4 w2 = *(const float4*)(Wp2 + c*32), w3 = *(const float4*)(Wp2 + c*32 + 4);
        __syncthreads();
        {
            uint4 h,l;
            split8(a0,a1,h,l); *(uint4*)&Ah[lr*APAD+lc]=h;      *(uint4*)&Al[lr*APAD+lc]=l;
            split8(a2,a3,h,l); *(uint4*)&Ah[(lr+64)*APAD+lc]=h; *(uint4*)&Al[(lr+64)*APAD+lc]=l;
            split8(w0,w1,h,l); *(uint4*)&Bh[lr*APAD+lc]=h;      *(uint4*)&Bl[lr*APAD+lc]=l;
            split8(w2,w3,h,l); *(uint4*)&Bh[(lr+64)*APAD+lc]=h; *(uint4*)&Bl[(lr+64)*APAD+lc]=l;
        }
        __syncthreads();
        GEMM_COMPUTE_128(0,  sAh, sAl, sBh, sBl);
        GEMM_COMPUTE_128(16, sAh, sAl, sBh, sBl);
    }

    // ---- staged epilogue ----
    __syncthreads();
    int gr = lane >> 2, ti = lane & 3;
    #pragma unroll
    for (int mf = 0; mf < 2; mf++)
        #pragma unroll
        for (int nf = 0; nf < 8; nf++)
            #pragma unroll
            for (int hh = 0; hh < 2; hh++) {
                int row = wm + mf*16 + gr + hh*8;
                int col = wn + nf*8 + ti*2;
                *(float2*)&stg[row*SP + col] =
                    make_float2(acc[mf*8+nf][hh*2], acc[mf*8+nf][hh*2+1]);
            }
    __syncthreads();

    float4 bz = *(const float4*)&bias[f0 + lane*4];
    #pragma unroll 4
    for (int it = 0; it < 16; it++) {
        int ml = it*8 + wid;
        int m = m0 + ml;
        float4 v = *(float4*)&stg[ml*SP + lane*4];
        v.x += bz.x; v.y += bz.y; v.z += bz.z; v.w += bz.w;
        if (mode < 3) {
            int s = m >> 1, b = m & 1;
            int f = f0 + lane*4, h = f >> 6, d = f & 63;
            float* dst = (mode==0) ? g_Q : (mode==1) ? g_K : g_V;
            *(float4*)&dst[(((size_t)(b*Hdim + h))*Sdim + s)*Ddim + d] = v;
        } else {
            int b = m >> 11, s = m & 2047;
            *(float4*)&outp[((size_t)s*Bdim + b)*Edim + f0 + lane*4] = v;
        }
    }
}

// Merged QKV projection: blockIdx.z selects {query->Q, key->K, value->V}.
__global__ void __launch_bounds__(256, 2)
mha_proj_qkv(const float* __restrict__ q, const float* __restrict__ k,
             const float* __restrict__ v,
             const float* __restrict__ Wq, const float* __restrict__ Wk,
             const float* __restrict__ Wv,
             const float* __restrict__ bq, const float* __restrict__ bk,
             const float* __restrict__ bv)
{
    extern __shared__ __align__(16) char dsm[];
    int z = blockIdx.z;
    const float* A    = (z==0) ? q  : (z==1) ? k  : v;
    const float* W    = (z==0) ? Wq : (z==1) ? Wk : Wv;
    const float* bias = (z==0) ? bq : (z==1) ? bk : bv;
    proj_core(A, W, bias, nullptr, z, dsm);
}

// Output projection (mode 3): A = g_ctx, result -> out [S,B,E].
__global__ void __launch_bounds__(256, 2)
mha_proj_o(const float* __restrict__ Wo, const float* __restrict__ bo,
           float* __restrict__ outp)
{
    extern __shared__ __align__(16) char dsm[];
    proj_core(g_ctx, Wo, bo, outp, 3, dsm);
}

// ---------------------------------------------------------------------------
// Scores+exp: attn[bh,q,k] = exp(0.125*(Q·K) + bias[q,k]) (unnormalized),
// plus per-(row, ktile) partial sums into g_psum. 128x128 tile, K=64.
// ---------------------------------------------------------------------------
__global__ void __launch_bounds__(256, 2)
mha_scores_mma(const float* __restrict__ bias, float* __restrict__ attn)
{
    extern __shared__ __align__(16) char dsm[];
    __nv_bfloat16* Ah = (__nv_bfloat16*)dsm;
    __nv_bfloat16* Al = Ah + 128*APAD;
    __nv_bfloat16* Bh = Al + 128*APAD;
    __nv_bfloat16* Bl = Bh + 128*APAD;
    float* stg = (float*)dsm;

    int tid = threadIdx.x, wid = tid >> 5, lane = tid & 31;
    int k0 = blockIdx.x << 7, q0 = blockIdx.y << 7, bh = blockIdx.z;
    int wm = (wid & 3) << 5, wn = (wid >> 2) << 6;
    const float* Qg = g_Q + ((size_t)bh*Sdim + q0)*Ddim;
    const float* Kg = g_K + ((size_t)bh*Sdim + k0)*Ddim;

    u32 sAh = smem_u32(Ah), sAl = smem_u32(Al), sBh = smem_u32(Bh), sBl = smem_u32(Bl);
    int a_r = (lane & 7) + ((lane >> 3) & 1) * 8;
    int a_c = ((lane >> 4) & 1) * 8;
    int b_pr = lane & 7;
    int b_pc = ((lane >> 3) & 1) * 8;
    int b_pn = (lane >> 4) * 8;

    int lr = tid >> 2, lc = (tid & 3) * 8;
    const float* Qp  = Qg + (size_t)lr*Ddim + lc;
    const float* Qp2 = Qp + (size_t)64*Ddim;
    const float* Kp  = Kg + (size_t)lr*Ddim + lc;
    const float* Kp2 = Kp + (size_t)64*Ddim;

    float acc[16][4];
    #pragma unroll
    for (int i = 0; i < 16; i++){ acc[i][0]=0.f; acc[i][1]=0.f; acc[i][2]=0.f; acc[i][3]=0.f; }

    for (int c = 0; c < 2; c++) {
        float4 a0 = *(const float4*)(Qp  + c*32), a1 = *(const float4*)(Qp  + c*32 + 4);
        float4 a2 = *(const float4*)(Qp2 + c*32), a3 = *(const float4*)(Qp2 + c*32 + 4);
        float4 w0 = *(const float4*)(Kp  + c*32), w1 = *(const float4*)(Kp  + c*32 + 4);
        float4 w2 = *(const float4*)(Kp2 + c*32), w3 = *(const float4*)(Kp2 + c*32 + 4);
        __syncthreads();
        {
            uint4 h,l;
            split8(a0,a1,h,l); *(uint4*)&Ah[lr*APAD+lc]=h;      *(uint4*)&Al[lr*APAD+lc]=l;
            split8(a2,a3,h,l); *(uint4*)&Ah[(lr+64)*APAD+lc]=h; *(uint4*)&Al[(lr+64)*APAD+lc]=l;
            split8(w0,w1,h,l); *(uint4*)&Bh[lr*APAD+lc]=h;      *(uint4*)&Bl[lr*APAD+lc]=l;
            split8(w2,w3,h,l); *(uint4*)&Bh[(lr+64)*APAD+lc]=h; *(uint4*)&Bl[(lr+64)*APAD+lc]=l;
        }
        __syncthreads();
        GEMM_COMPUTE_128(0,  sAh, sAl, sBh, sBl);
        GEMM_COMPUTE_128(16, sAh, sAl, sBh, sBl);
    }

    // ---- staged epilogue: exp + partial row sums ----
    __syncthreads();
    int gr = lane >> 2, ti = lane & 3;
    #pragma unroll
    for (int mf = 0; mf < 2; mf++)
        #pragma unroll
        for (int nf = 0; nf < 8; nf++)
            #pragma unroll
            for (int hh = 0; hh < 2; hh++) {
                int row = wm + mf*16 + gr + hh*8;
                int col = wn + nf*8 + ti*2;
                *(float2*)&stg[row*SP + col] =
                    make_float2(acc[mf*8+nf][hh*2], acc[mf*8+nf][hh*2+1]);
            }
    __syncthreads();

    #pragma unroll 4
    for (int it = 0; it < 16; it++) {
        int r = it*8 + wid;
        float4 v = *(float4*)&stg[r*SP + lane*4];
        float4 bz = *(const float4*)&bias[(size_t)(q0+r)*Sdim + k0 + lane*4];
        float4 e;
        e.x = __expf(v.x*0.125f + bz.x);
        e.y = __expf(v.y*0.125f + bz.y);
        e.z = __expf(v.z*0.125f + bz.z);
        e.w = __expf(v.w*0.125f + bz.w);
        *(float4*)&attn[((size_t)bh*Sdim + q0 + r)*Sdim + k0 + lane*4] = e;
        float s4 = (e.x + e.y) + (e.z + e.w);
        #pragma unroll
        for (int o=16;o>0;o>>=1) s4 += __shfl_xor_sync(0xffffffffu, s4, o);
        if (lane == 0)
            g_psum[((size_t)bh*Sdim + q0 + r)*16 + (k0 >> 7)] = s4;
    }
}

// ---------------------------------------------------------------------------
// Row-sum reduce: g_inv[row] = 1 / sum(g_psum[row][0..15]).
// ---------------------------------------------------------------------------
__global__ void __launch_bounds__(256)
mha_rowsum(void)
{
    int row = blockIdx.x*256 + threadIdx.x;
    const float4* p = (const float4*)&g_psum[(size_t)row*16];
    float4 a = p[0], b = p[1], c = p[2], d = p[3];
    float s = ((a.x+a.y)+(a.z+a.w)) + ((b.x+b.y)+(b.z+b.w))
            + ((c.x+c.y)+(c.z+c.w)) + ((d.x+d.y)+(d.z+d.w));
    g_inv[row] = 1.0f / s;
}

// ---------------------------------------------------------------------------
// Context: normalizes attn in place (each CTA owns a 64-row strip exclusively),
// and ctx[b,s,h*64+d] = sum_k attn_norm[bh,s,k] * V[bh,k,d].
// 64(q) x 64(d) tile, K=2048 in 64 chunks of 32. 2x4 warp grid, 3 CTAs/SM.
// ---------------------------------------------------------------------------
__global__ void __launch_bounds__(256, 3)
mha_ctx_mma(float* __restrict__ attn)
{
    extern __shared__ __align__(16) char dsm[];
    __nv_bfloat16* Ah = (__nv_bfloat16*)dsm;          // 64 x APAD
    __nv_bfloat16* Al = Ah + 64*APAD;
    __nv_bfloat16* Vh = Al + 64*APAD;                 // 32 x VPAD
    __nv_bfloat16* Vl = Vh + 32*VPAD;
    float* stg = (float*)dsm;                         // 64 x CP fp32 (aliases)

    int tid = threadIdx.x, wid = tid >> 5, lane = tid & 31;
    int q0 = blockIdx.x << 6, bh = blockIdx.y;
    int b = bh >> 4, h = bh & 15;
    int wm = (wid & 1) << 5, wn = (wid >> 1) << 4;    // 2(m) x 4(n), 32x16 per warp
    float* Ag = attn + ((size_t)bh*Sdim + q0)*Sdim;
    const float* Vg = g_V + (size_t)bh*Sdim*Ddim;

    u32 sAh = smem_u32(Ah), sAl = smem_u32(Al), sVh = smem_u32(Vh), sVl = smem_u32(Vl);
    int a_r = (lane & 7) + ((lane >> 3) & 1) * 8;
    int a_c = ((lane >> 4) & 1) * 8;

    int lr = tid >> 2, lc = (tid & 3) * 8;       // attn tile loads (64 rows x 32)
    int vr = tid >> 3, vc = (tid & 7) * 8;       // V tile loads (32 rows x 64)
    float* Ap = Ag + (size_t)lr*Sdim + lc;
    const float* Vp = Vg + (size_t)vr*Ddim + vc;

    float invA = g_inv[(size_t)bh*Sdim + q0 + lr];

    float acc[4][4];
    #pragma unroll
    for (int i = 0; i < 4; i++){ acc[i][0]=0.f; acc[i][1]=0.f; acc[i][2]=0.f; acc[i][3]=0.f; }

    for (int c = 0; c < 64; c++) {
        float4 a0 = *(const float4*)(Ap + c*32), a1 = *(const float4*)(Ap + c*32 + 4);
        float4 v0 = *(const float4*)(Vp + (size_t)c*32*Ddim);
        float4 v1 = *(const float4*)(Vp + (size_t)c*32*Ddim + 4);
        a0.x*=invA; a0.y*=invA; a0.z*=invA; a0.w*=invA;
        a1.x*=invA; a1.y*=invA; a1.z*=invA; a1.w*=invA;
        *(float4*)(Ap + c*32)     = a0;
        *(float4*)(Ap + c*32 + 4) = a1;
        __syncthreads();
        {
            uint4 h4,l4;
            split8(a0,a1,h4,l4); *(uint4*)&Ah[lr*APAD+lc]=h4; *(uint4*)&Al[lr*APAD+lc]=l4;
            split8(v0,v1,h4,l4); *(uint4*)&Vh[vr*VPAD+vc]=h4; *(uint4*)&Vl[vr*VPAD+vc]=l4;
        }
        __syncthreads();
        #pragma unroll
        for (int ks = 0; ks < 32; ks += 16) {
            u32 ah0[4], ah1[4], al0[4], al1[4];
            u32 aoff0 = (u32)((wm      + a_r)*APAD + ks + a_c) * 2;
            u32 aoff1 = (u32)((wm + 16 + a_r)*APAD + ks + a_c) * 2;
            ldsm4(ah0, sAh + aoff0); ldsm4(ah1, sAh + aoff1);
            ldsm4(al0, sAl + aoff0); ldsm4(al1, sAl + aoff1);
            #pragma unroll
            for (int nf = 0; nf < 2; nf++) {
                u32 bo = (u32)((ks + (lane & 15))*VPAD + wn + nf*8) * 2;
                u32 bhf[2], blf[2];
                ldsm2t(bhf, sVh + bo); ldsm2t(blf, sVl + bo);
                mma16816(acc[nf],   ah0, bhf);
                mma16816(acc[nf],   ah0, blf);
                mma16816(acc[nf],   al0, bhf);
                mma16816(acc[2+nf], ah1, bhf);
                mma16816(acc[2+nf], ah1, blf);
                mma16816(acc[2+nf], al1, bhf);
            }
        }
        __syncthreads();
    }

    // ---- staged epilogue ----
    int gr = lane >> 2, ti = lane & 3;
    #pragma unroll
    for (int mf = 0; mf < 2; mf++)
        #pragma unroll
        for (int nf = 0; nf < 2; nf++)
            #pragma unroll
            for (int hh = 0; hh < 2; hh++) {
                int row = wm + mf*16 + gr + hh*8;
                int col = wn + nf*8 + ti*2;
                *(float2*)&stg[row*CP + col] =
                    make_float2(acc[mf*2+nf][hh*2], acc[mf*2+nf][hh*2+1]);
            }
    __syncthreads();

    // 8 warps x 2 rows x 4 iters = 64 rows
    #pragma unroll 4
    for (int it = 0; it < 4; it++) {
        int r = it*16 + wid*2 + (lane >> 4);
        float4 v = *(float4*)&stg[r*CP + (lane & 15)*4];
        int s = q0 + r;
        *(float4*)&g_ctx[((size_t)b*Sdim + s)*Edim + h*64 + (lane & 15)*4] = v;
    }
}

extern "C" void kernel_launch(void* const* d_in, const int* in_sizes, int n_in,
                              void* d_out, int out_size) {
    const float* query = (const float*)d_in[0];
    const float* key_  = (const float*)d_in[1];
    const float* value = (const float*)d_in[2];
    const float* Wq = (const float*)d_in[3];
    const float* bq = (const float*)d_in[4];
    const float* Wk = (const float*)d_in[5];
    const float* bk = (const float*)d_in[6];
    const float* Wv = (const float*)d_in[7];
    const float* bv = (const float*)d_in[8];
    const float* Wo = (const float*)d_in[9];
    const float* bo = (const float*)d_in[10];
    const float* bias_matrix = (const float*)d_in[11];

    float* out  = (float*)d_out;                    // [S,B,E]
    float* attn = out + (size_t)Sdim*Bdim*Edim;     // [B,H,S,S]

    cudaFuncSetAttribute(mha_proj_qkv,   cudaFuncAttributeMaxDynamicSharedMemorySize, PROJ_DSM);
    cudaFuncSetAttribute(mha_proj_o,     cudaFuncAttributeMaxDynamicSharedMemorySize, PROJ_DSM);
    cudaFuncSetAttribute(mha_scores_mma, cudaFuncAttributeMaxDynamicSharedMemorySize, PROJ_DSM);
    cudaFuncSetAttribute(mha_ctx_mma,    cudaFuncAttributeMaxDynamicSharedMemorySize, CTX_DSM);

    dim3 gqkv(Edim/128, (Sdim*Bdim)/128, 3);        // (8, 32, 3) merged QKV
    mha_proj_qkv<<<gqkv, 256, PROJ_DSM>>>(query, key_, value, Wq, Wk, Wv, bq, bk, bv);

    dim3 gsc(Sdim/128, Sdim/128, Bdim*Hdim);        // (16,16,32)
    mha_scores_mma<<<gsc, 256, PROJ_DSM>>>(bias_matrix, attn);

    mha_rowsum<<<(Bdim*Hdim*Sdim)/256, 256>>>();

    dim3 gctx(Sdim/64, Bdim*Hdim);                  // (32,32) = 1024 CTAs
    mha_ctx_mma<<<gctx, 256, CTX_DSM>>>(attn);

    dim3 gproj(Edim/128, (Sdim*Bdim)/128);          // (8, 32)
    mha_proj_o<<<gproj, 256, PROJ_DSM>>>(Wo, bo, out);
}

// round 13
// speedup vs baseline: 1.0348x; 1.0348x over previous
#include <cuda_runtime.h>
#include <cuda_bf16.h>
#include <cstdint>

#define Sdim 2048
#define Bdim 2
#define Edim 1024
#define Hdim 16
#define Ddim 64
#define APAD 40   // bf16 elems per smem tile row (80B stride: conflict-free ldmatrix)
#define VPAD 72   // ctx V tile row pad (144B stride: conflict-free trans ldmatrix)
#define SP   132  // fp32 staging pad (proj/scores) — 528B row stride, 16B aligned
#define CP   68   // fp32 staging pad (ctx) — 272B row stride, 16B aligned

typedef uint32_t u32;

// scratch: static device arrays (allocation-free rule)
__device__ float g_Q[Bdim*Hdim*Sdim*Ddim];       // [B,H,S,D]
__device__ float g_K[Bdim*Hdim*Sdim*Ddim];       // [B,H,S,D]
__device__ float g_V[Bdim*Hdim*Sdim*Ddim];       // [B,H,S,D]
__device__ float g_ctx2[2*Bdim*Sdim*Edim];       // split-K partials [2][B,S,E]
__device__ float g_psum[Bdim*Hdim*Sdim*16];      // per-(row, ktile) exp partial sums
__device__ float g_inv[Bdim*Hdim*Sdim];          // 1/rowsum

__device__ __forceinline__ u32 smem_u32(const void* p){
    u32 a;
    asm("{ .reg .u64 t; cvta.to.shared.u64 t, %1; cvt.u32.u64 %0, t; }" : "=r"(a) : "l"(p));
    return a;
}
__device__ __forceinline__ void ldsm4(u32 r[4], u32 addr){
    asm volatile("ldmatrix.sync.aligned.m8n8.x4.shared.b16 {%0,%1,%2,%3}, [%4];"
        : "=r"(r[0]),"=r"(r[1]),"=r"(r[2]),"=r"(r[3]) : "r"(addr));
}
__device__ __forceinline__ void ldsm2t(u32 r[2], u32 addr){
    asm volatile("ldmatrix.sync.aligned.m8n8.x2.trans.shared.b16 {%0,%1}, [%2];"
        : "=r"(r[0]),"=r"(r[1]) : "r"(addr));
}
__device__ __forceinline__ void mma16816(float c[4], const u32 a[4], const u32 b[2]){
    asm volatile("mma.sync.aligned.m16n8k16.row.col.f32.bf16.bf16.f32 "
        "{%0,%1,%2,%3}, {%4,%5,%6,%7}, {%8,%9}, {%0,%1,%2,%3};"
        : "+f"(c[0]),"+f"(c[1]),"+f"(c[2]),"+f"(c[3])
        : "r"(a[0]),"r"(a[1]),"r"(a[2]),"r"(a[3]), "r"(b[0]),"r"(b[1]));
}

// 8 consecutive floats -> 16B hi-bf16 uint4 + 16B lo-bf16 uint4
__device__ __forceinline__ void split8(float4 a, float4 b, uint4& hi, uint4& lo){
    __nv_bfloat16 h0=__float2bfloat16(a.x), h1=__float2bfloat16(a.y),
                  h2=__float2bfloat16(a.z), h3=__float2bfloat16(a.w),
                  h4=__float2bfloat16(b.x), h5=__float2bfloat16(b.y),
                  h6=__float2bfloat16(b.z), h7=__float2bfloat16(b.w);
    __nv_bfloat162 p0=__halves2bfloat162(h0,h1), p1=__halves2bfloat162(h2,h3),
                   p2=__halves2bfloat162(h4,h5), p3=__halves2bfloat162(h6,h7);
    hi = make_uint4(*(u32*)&p0, *(u32*)&p1, *(u32*)&p2, *(u32*)&p3);
    __nv_bfloat162 q0=__floats2bfloat162_rn(a.x-__bfloat162float(h0), a.y-__bfloat162float(h1));
    __nv_bfloat162 q1=__floats2bfloat162_rn(a.z-__bfloat162float(h2), a.w-__bfloat162float(h3));
    __nv_bfloat162 q2=__floats2bfloat162_rn(b.x-__bfloat162float(h4), b.y-__bfloat162float(h5));
    __nv_bfloat162 q3=__floats2bfloat162_rn(b.z-__bfloat162float(h6), b.w-__bfloat162float(h7));
    lo = make_uint4(*(u32*)&q0, *(u32*)&q1, *(u32*)&q2, *(u32*)&q3);
}

#define PROJ_DSM (128*SP*4)
#define CTX_DSM  (128*CP*4)

// GEMM compute for one 16-wide K slab (4x2 warps, 8 nf), B pairs via ldsm4.
#define GEMM_COMPUTE_128(KS, sAh, sAl, sBh, sBl)                               \
    do {                                                                       \
        u32 ah0[4], ah1[4], al0[4], al1[4];                                    \
        u32 aoff0 = (sAh) + (u32)((wm      + a_r)*APAD + (KS) + a_c) * 2;      \
        u32 aoff1 = (sAh) + (u32)((wm + 16 + a_r)*APAD + (KS) + a_c) * 2;      \
        u32 loff0 = (sAl) + (u32)((wm      + a_r)*APAD + (KS) + a_c) * 2;      \
        u32 loff1 = (sAl) + (u32)((wm + 16 + a_r)*APAD + (KS) + a_c) * 2;      \
        ldsm4(ah0, aoff0); ldsm4(ah1, aoff1);                                  \
        ldsm4(al0, loff0); ldsm4(al1, loff1);                                  \
        _Pragma("unroll")                                                      \
        for (int nf = 0; nf < 8; nf += 2) {                                    \
            u32 bo = (u32)((wn + nf*8 + b_pn + b_pr)*APAD + (KS) + b_pc) * 2;  \
            u32 bh4[4], bl4[4];                                                \
            ldsm4(bh4, (sBh) + bo); ldsm4(bl4, (sBl) + bo);                    \
            mma16816(acc[nf],     ah0, bh4);                                   \
            mma16816(acc[nf],     ah0, bl4);                                   \
            mma16816(acc[nf],     al0, bh4);                                   \
            mma16816(acc[8+nf],   ah1, bh4);                                   \
            mma16816(acc[8+nf],   ah1, bl4);                                   \
            mma16816(acc[8+nf],   al1, bh4);                                   \
            mma16816(acc[nf+1],   ah0, bh4+2);                                 \
            mma16816(acc[nf+1],   ah0, bl4+2);                                 \
            mma16816(acc[nf+1],   al0, bh4+2);                                 \
            mma16816(acc[8+nf+1], ah1, bh4+2);                                 \
            mma16816(acc[8+nf+1], ah1, bl4+2);                                 \
            mma16816(acc[8+nf+1], al1, bh4+2);                                 \
        }                                                                      \
    } while (0)

// ---------------------------------------------------------------------------
// Shared projection core: out[m,f] = sum_e A[m,e]*W[f,e] + bias[f].
// A2 != nullptr: loader adds A2 elementwise (split-K ctx partials).
// modes 0/1/2: scatter to g_Q/g_K/g_V as [B,H,S,D]; 3: -> outp [S,B,E].
// ---------------------------------------------------------------------------
__device__ __forceinline__ void proj_core(
    const float* __restrict__ A, const float* __restrict__ A2,
    const float* __restrict__ W,
    const float* __restrict__ bias, float* __restrict__ outp, int mode, char* dsm)
{
    __nv_bfloat16* Ah = (__nv_bfloat16*)dsm;
    __nv_bfloat16* Al = Ah + 128*APAD;
    __nv_bfloat16* Bh = Al + 128*APAD;
    __nv_bfloat16* Bl = Bh + 128*APAD;
    float* stg = (float*)dsm;

    int tid = threadIdx.x, wid = tid >> 5, lane = tid & 31;
    int m0 = blockIdx.y << 7, f0 = blockIdx.x << 7;
    int wm = (wid & 3) << 5, wn = (wid >> 2) << 6;

    u32 sAh = smem_u32(Ah), sAl = smem_u32(Al), sBh = smem_u32(Bh), sBl = smem_u32(Bl);

    int a_r = (lane & 7) + ((lane >> 3) & 1) * 8;
    int a_c = ((lane >> 4) & 1) * 8;
    int b_pr = lane & 7;
    int b_pc = ((lane >> 3) & 1) * 8;
    int b_pn = (lane >> 4) * 8;

    int lr = tid >> 2, lc = (tid & 3) * 8;

    float acc[16][4];
    #pragma unroll
    for (int i = 0; i < 16; i++){ acc[i][0]=0.f; acc[i][1]=0.f; acc[i][2]=0.f; acc[i][3]=0.f; }

    size_t aoffs  = (size_t)(m0 + lr)*Edim + lc;
    const float* Ap  = A + aoffs;
    const float* Ap2 = Ap + (size_t)64*Edim;
    const float* Bp  = A2 ? (A2 + aoffs) : nullptr;
    const float* Bp2 = A2 ? (Bp + (size_t)64*Edim) : nullptr;
    const float* Wp  = W + (size_t)(f0 + lr)*Edim + lc;
    const float* Wp2 = Wp + (size_t)64*Edim;

    for (int c = 0; c < 32; c++) {
        float4 a0 = *(const float4*)(Ap  + c*32), a1 = *(const float4*)(Ap  + c*32 + 4);
        float4 a2 = *(const float4*)(Ap2 + c*32), a3 = *(const float4*)(Ap2 + c*32 + 4);
        if (A2) {
            float4 x0 = *(const float4*)(Bp  + c*32), x1 = *(const float4*)(Bp  + c*32 + 4);
            float4 x2 = *(const float4*)(Bp2 + c*32), x3 = *(const float4*)(Bp2 + c*32 + 4);
            a0.x+=x0.x; a0.y+=x0.y; a0.z+=x0.z; a0.w+=x0.w;
            a1.x+=x1.x; a1.y+=x1.y; a1.z+=x1.z; a1.w+=x1.w;
            a2.x+=x2.x; a2.y+=x2.y; a2.z+=x2.z; a2.w+=x2.w;
            a3.x+=x3.x; a3.y+=x3.y; a3.z+=x3.z; a3.w+=x3.w;
        }
        float4 w0 = *(const float4*)(Wp  + c*32), w1 = *(const float4*)(Wp  + c*32 + 4);
        float4 w2 = *(const float4*)(Wp2 + c*32), w3 = *(const float4*)(Wp2 + c*32 + 4);
        __syncthreads();
        {
            uint4 h,l;
            split8(a0,a1,h,l); *(uint4*)&Ah[lr*APAD+lc]=h;      *(uint4*)&Al[lr*APAD+lc]=l;
            split8(a2,a3,h,l); *(uint4*)&Ah[(lr+64)*APAD+lc]=h; *(uint4*)&Al[(lr+64)*APAD+lc]=l;
            split8(w0,w1,h,l); *(uint4*)&Bh[lr*APAD+lc]=h;      *(uint4*)&Bl[lr*APAD+lc]=l;
            split8(w2,w3,h,l); *(uint4*)&Bh[(lr+64)*APAD+lc]=h; *(uint4*)&Bl[(lr+64)*APAD+lc]=l;
        }
        __syncthreads();
        GEMM_COMPUTE_128(0,  sAh, sAl, sBh, sBl);
        GEMM_COMPUTE_128(16, sAh, sAl, sBh, sBl);
    }

    // ---- staged epilogue ----
    __syncthreads();
    int gr = lane >> 2, ti = lane & 3;
    #pragma unroll
    for (int mf = 0; mf < 2; mf++)
        #pragma unroll
        for (int nf = 0; nf < 8; nf++)
            #pragma unroll
            for (int hh = 0; hh < 2; hh++) {
                int row = wm + mf*16 + gr + hh*8;
                int col = wn + nf*8 + ti*2;
                *(float2*)&stg[row*SP + col] =
                    make_float2(acc[mf*8+nf][hh*2], acc[mf*8+nf][hh*2+1]);
            }
    __syncthreads();

    float4 bz = *(const float4*)&bias[f0 + lane*4];
    #pragma unroll 4
    for (int it = 0; it < 16; it++) {
        int ml = it*8 + wid;
        int m = m0 + ml;
        float4 v = *(float4*)&stg[ml*SP + lane*4];
        v.x += bz.x; v.y += bz.y; v.z += bz.z; v.w += bz.w;
        if (mode < 3) {
            int s = m >> 1, b = m & 1;
            int f = f0 + lane*4, h = f >> 6, d = f & 63;
            float* dst = (mode==0) ? g_Q : (mode==1) ? g_K : g_V;
            *(float4*)&dst[(((size_t)(b*Hdim + h))*Sdim + s)*Ddim + d] = v;
        } else {
            int b = m >> 11, s = m & 2047;
            *(float4*)&outp[((size_t)s*Bdim + b)*Edim + f0 + lane*4] = v;
        }
    }
}

// Merged QKV projection: blockIdx.z selects {query->Q, key->K, value->V}.
__global__ void __launch_bounds__(256, 2)
mha_proj_qkv(const float* __restrict__ q, const float* __restrict__ k,
             const float* __restrict__ v,
             const float* __restrict__ Wq, const float* __restrict__ Wk,
             const float* __restrict__ Wv,
             const float* __restrict__ bq, const float* __restrict__ bk,
             const float* __restrict__ bv)
{
    extern __shared__ __align__(16) char dsm[];
    int z = blockIdx.z;
    const float* A    = (z==0) ? q  : (z==1) ? k  : v;
    const float* W    = (z==0) ? Wq : (z==1) ? Wk : Wv;
    const float* bias = (z==0) ? bq : (z==1) ? bk : bv;
    proj_core(A, nullptr, W, bias, nullptr, z, dsm);
}

// Output projection (mode 3): A = g_ctx2[0] + g_ctx2[1], result -> out [S,B,E].
__global__ void __launch_bounds__(256, 2)
mha_proj_o(const float* __restrict__ Wo, const float* __restrict__ bo,
           float* __restrict__ outp)
{
    extern __shared__ __align__(16) char dsm[];
    proj_core(g_ctx2, g_ctx2 + (size_t)Bdim*Sdim*Edim, Wo, bo, outp, 3, dsm);
}

// ---------------------------------------------------------------------------
// Scores+exp: attn[bh,q,k] = exp(0.125*(Q·K) + bias[q,k]) (unnormalized),
// plus per-(row, ktile) partial sums into g_psum. 128x128 tile, K=64.
// ---------------------------------------------------------------------------
__global__ void __launch_bounds__(256, 2)
mha_scores_mma(const float* __restrict__ bias, float* __restrict__ attn)
{
    extern __shared__ __align__(16) char dsm[];
    __nv_bfloat16* Ah = (__nv_bfloat16*)dsm;
    __nv_bfloat16* Al = Ah + 128*APAD;
    __nv_bfloat16* Bh = Al + 128*APAD;
    __nv_bfloat16* Bl = Bh + 128*APAD;
    float* stg = (float*)dsm;

    int tid = threadIdx.x, wid = tid >> 5, lane = tid & 31;
    int k0 = blockIdx.x << 7, q0 = blockIdx.y << 7, bh = blockIdx.z;
    int wm = (wid & 3) << 5, wn = (wid >> 2) << 6;
    const float* Qg = g_Q + ((size_t)bh*Sdim + q0)*Ddim;
    const float* Kg = g_K + ((size_t)bh*Sdim + k0)*Ddim;

    u32 sAh = smem_u32(Ah), sAl = smem_u32(Al), sBh = smem_u32(Bh), sBl = smem_u32(Bl);
    int a_r = (lane & 7) + ((lane >> 3) & 1) * 8;
    int a_c = ((lane >> 4) & 1) * 8;
    int b_pr = lane & 7;
    int b_pc = ((lane >> 3) & 1) * 8;
    int b_pn = (lane >> 4) * 8;

    int lr = tid >> 2, lc = (tid & 3) * 8;
    const float* Qp  = Qg + (size_t)lr*Ddim + lc;
    const float* Qp2 = Qp + (size_t)64*Ddim;
    const float* Kp  = Kg + (size_t)lr*Ddim + lc;
    const float* Kp2 = Kp + (size_t)64*Ddim;

    float acc[16][4];
    #pragma unroll
    for (int i = 0; i < 16; i++){ acc[i][0]=0.f; acc[i][1]=0.f; acc[i][2]=0.f; acc[i][3]=0.f; }

    for (int c = 0; c < 2; c++) {
        float4 a0 = *(const float4*)(Qp  + c*32), a1 = *(const float4*)(Qp  + c*32 + 4);
        float4 a2 = *(const float4*)(Qp2 + c*32), a3 = *(const float4*)(Qp2 + c*32 + 4);
        float4 w0 = *(const float4*)(Kp  + c*32), w1 = *(const float4*)(Kp  + c*32 + 4);
        float4 w2 = *(const float4*)(Kp2 + c*32), w3 = *(const float4*)(Kp2 + c*32 + 4);
        __syncthreads();
        {
            uint4 h,l;
            split8(a0,a1,h,l); *(uint4*)&Ah[lr*APAD+lc]=h;      *(uint4*)&Al[lr*APAD+lc]=l;
            split8(a2,a3,h,l); *(uint4*)&Ah[(lr+64)*APAD+lc]=h; *(uint4*)&Al[(lr+64)*APAD+lc]=l;
            split8(w0,w1,h,l); *(uint4*)&Bh[lr*APAD+lc]=h;      *(uint4*)&Bl[lr*APAD+lc]=l;
            split8(w2,w3,h,l); *(uint4*)&Bh[(lr+64)*APAD+lc]=h; *(uint4*)&Bl[(lr+64)*APAD+lc]=l;
        }
        __syncthreads();
        GEMM_COMPUTE_128(0,  sAh, sAl, sBh, sBl);
        GEMM_COMPUTE_128(16, sAh, sAl, sBh, sBl);
    }

    // ---- staged epilogue: exp + partial row sums ----
    __syncthreads();
    int gr = lane >> 2, ti = lane & 3;
    #pragma unroll
    for (int mf = 0; mf < 2; mf++)
        #pragma unroll
        for (int nf = 0; nf < 8; nf++)
            #pragma unroll
            for (int hh = 0; hh < 2; hh++) {
                int row = wm + mf*16 + gr + hh*8;
                int col = wn + nf*8 + ti*2;
                *(float2*)&stg[row*SP + col] =
                    make_float2(acc[mf*8+nf][hh*2], acc[mf*8+nf][hh*2+1]);
            }
    __syncthreads();

    #pragma unroll 4
    for (int it = 0; it < 16; it++) {
        int r = it*8 + wid;
        float4 v = *(float4*)&stg[r*SP + lane*4];
        float4 bz = *(const float4*)&bias[(size_t)(q0+r)*Sdim + k0 + lane*4];
        float4 e;
        e.x = __expf(v.x*0.125f + bz.x);
        e.y = __expf(v.y*0.125f + bz.y);
        e.z = __expf(v.z*0.125f + bz.z);
        e.w = __expf(v.w*0.125f + bz.w);
        *(float4*)&attn[((size_t)bh*Sdim + q0 + r)*Sdim + k0 + lane*4] = e;
        float s4 = (e.x + e.y) + (e.z + e.w);
        #pragma unroll
        for (int o=16;o>0;o>>=1) s4 += __shfl_xor_sync(0xffffffffu, s4, o);
        if (lane == 0)
            g_psum[((size_t)bh*Sdim + q0 + r)*16 + (k0 >> 7)] = s4;
    }
}

// ---------------------------------------------------------------------------
// Row-sum reduce: g_inv[row] = 1 / sum(g_psum[row][0..15]).
// ---------------------------------------------------------------------------
__global__ void __launch_bounds__(256)
mha_rowsum(void)
{
    int row = blockIdx.x*256 + threadIdx.x;
    const float4* p = (const float4*)&g_psum[(size_t)row*16];
    float4 a = p[0], b = p[1], c = p[2], d = p[3];
    float s = ((a.x+a.y)+(a.z+a.w)) + ((b.x+b.y)+(b.z+b.w))
            + ((c.x+c.y)+(c.z+c.w)) + ((d.x+d.y)+(d.z+d.w));
    g_inv[row] = 1.0f / s;
}

// ---------------------------------------------------------------------------
// Context (split-K=2): CTA (qtile, bh, khalf) normalizes its attn strip-half
// in place and accumulates partial ctx over K in [khalf*1024, +1024) into
// g_ctx2[khalf]. 128(q) x 64(d) tile, 32 chunks of 32.
// ---------------------------------------------------------------------------
__global__ void __launch_bounds__(256, 2)
mha_ctx_mma(float* __restrict__ attn)
{
    extern __shared__ __align__(16) char dsm[];
    __nv_bfloat16* Ah = (__nv_bfloat16*)dsm;
    __nv_bfloat16* Al = Ah + 128*APAD;
    __nv_bfloat16* Vh = Al + 128*APAD;          // 32 x VPAD
    __nv_bfloat16* Vl = Vh + 32*VPAD;
    float* stg = (float*)dsm;

    int tid = threadIdx.x, wid = tid >> 5, lane = tid & 31;
    int q0 = blockIdx.x << 7, bh = blockIdx.y;
    int khalf = blockIdx.z, kbase = khalf << 10;
    int b = bh >> 4, h = bh & 15;
    int wm = (wid & 3) << 5, wn = (wid >> 2) << 5;
    float* Ag = attn + ((size_t)bh*Sdim + q0)*Sdim + kbase;
    const float* Vg = g_V + ((size_t)bh*Sdim + kbase)*Ddim;
    float* ctxo = g_ctx2 + (size_t)khalf*Bdim*Sdim*Edim;

    u32 sAh = smem_u32(Ah), sAl = smem_u32(Al), sVh = smem_u32(Vh), sVl = smem_u32(Vl);
    int a_r = (lane & 7) + ((lane >> 3) & 1) * 8;
    int a_c = ((lane >> 4) & 1) * 8;

    int lr = tid >> 2, lc = (tid & 3) * 8;       // attn tile loads (128 rows x 32)
    int vr = tid >> 3, vc = (tid & 7) * 8;       // V tile loads (32 rows x 64)
    float* Ap  = Ag + (size_t)lr*Sdim + lc;
    float* Ap2 = Ap + (size_t)64*Sdim;
    const float* Vp = Vg + (size_t)vr*Ddim + vc;

    float invA  = g_inv[(size_t)bh*Sdim + q0 + lr];
    float invA2 = g_inv[(size_t)bh*Sdim + q0 + lr + 64];

    float acc[8][4];
    #pragma unroll
    for (int i = 0; i < 8; i++){ acc[i][0]=0.f; acc[i][1]=0.f; acc[i][2]=0.f; acc[i][3]=0.f; }

    for (int c = 0; c < 32; c++) {
        float4 a0 = *(const float4*)(Ap  + c*32), a1 = *(const float4*)(Ap  + c*32 + 4);
        float4 a2 = *(const float4*)(Ap2 + c*32), a3 = *(const float4*)(Ap2 + c*32 + 4);
        float4 v0 = *(const float4*)(Vp + (size_t)c*32*Ddim);
        float4 v1 = *(const float4*)(Vp + (size_t)c*32*Ddim + 4);
        a0.x*=invA;  a0.y*=invA;  a0.z*=invA;  a0.w*=invA;
        a1.x*=invA;  a1.y*=invA;  a1.z*=invA;  a1.w*=invA;
        a2.x*=invA2; a2.y*=invA2; a2.z*=invA2; a2.w*=invA2;
        a3.x*=invA2; a3.y*=invA2; a3.z*=invA2; a3.w*=invA2;
        *(float4*)(Ap  + c*32)     = a0;
        *(float4*)(Ap  + c*32 + 4) = a1;
        *(float4*)(Ap2 + c*32)     = a2;
        *(float4*)(Ap2 + c*32 + 4) = a3;
        __syncthreads();
        {
            uint4 h4,l4;
            split8(a0,a1,h4,l4); *(uint4*)&Ah[lr*APAD+lc]=h4;      *(uint4*)&Al[lr*APAD+lc]=l4;
            split8(a2,a3,h4,l4); *(uint4*)&Ah[(lr+64)*APAD+lc]=h4; *(uint4*)&Al[(lr+64)*APAD+lc]=l4;
            split8(v0,v1,h4,l4); *(uint4*)&Vh[vr*VPAD+vc]=h4;      *(uint4*)&Vl[vr*VPAD+vc]=l4;
        }
        __syncthreads();
        #pragma unroll
        for (int ks = 0; ks < 32; ks += 16) {
            u32 ah0[4], ah1[4], al0[4], al1[4];
            u32 aoff0 = (u32)((wm      + a_r)*APAD + ks + a_c) * 2;
            u32 aoff1 = (u32)((wm + 16 + a_r)*APAD + ks + a_c) * 2;
            ldsm4(ah0, sAh + aoff0); ldsm4(ah1, sAh + aoff1);
            ldsm4(al0, sAl + aoff0); ldsm4(al1, sAl + aoff1);
            #pragma unroll
            for (int nf = 0; nf < 4; nf++) {
                u32 bo = (u32)((ks + (lane & 15))*VPAD + wn + nf*8) * 2;
                u32 bhf[2], blf[2];
                ldsm2t(bhf, sVh + bo); ldsm2t(blf, sVl + bo);
                mma16816(acc[nf],   ah0, bhf);
                mma16816(acc[nf],   ah0, blf);
                mma16816(acc[nf],   al0, bhf);
                mma16816(acc[4+nf], ah1, bhf);
                mma16816(acc[4+nf], ah1, blf);
                mma16816(acc[4+nf], al1, bhf);
            }
        }
    }

    // ---- staged epilogue (partial sums to this khalf's buffer) ----
    __syncthreads();
    int gr = lane >> 2, ti = lane & 3;
    #pragma unroll
    for (int mf = 0; mf < 2; mf++)
        #pragma unroll
        for (int nf = 0; nf < 4; nf++)
            #pragma unroll
            for (int hh = 0; hh < 2; hh++) {
                int row = wm + mf*16 + gr + hh*8;
                int col = wn + nf*8 + ti*2;
                *(float2*)&stg[row*CP + col] =
                    make_float2(acc[mf*4+nf][hh*2], acc[mf*4+nf][hh*2+1]);
            }
    __syncthreads();

    #pragma unroll 4
    for (int it = 0; it < 8; it++) {
        int r = it*16 + wid*2 + (lane >> 4);
        float4 v = *(float4*)&stg[r*CP + (lane & 15)*4];
        int s = q0 + r;
        *(float4*)&ctxo[((size_t)b*Sdim + s)*Edim + h*64 + (lane & 15)*4] = v;
    }
}

extern "C" void kernel_launch(void* const* d_in, const int* in_sizes, int n_in,
                              void* d_out, int out_size) {
    const float* query = (const float*)d_in[0];
    const float* key_  = (const float*)d_in[1];
    const float* value = (const float*)d_in[2];
    const float* Wq = (const float*)d_in[3];
    const float* bq = (const float*)d_in[4];
    const float* Wk = (const float*)d_in[5];
    const float* bk = (const float*)d_in[6];
    const float* Wv = (const float*)d_in[7];
    const float* bv = (const float*)d_in[8];
    const float* Wo = (const float*)d_in[9];
    const float* bo = (const float*)d_in[10];
    const float* bias_matrix = (const float*)d_in[11];

    float* out  = (float*)d_out;                    // [S,B,E]
    float* attn = out + (size_t)Sdim*Bdim*Edim;     // [B,H,S,S]

    cudaFuncSetAttribute(mha_proj_qkv,   cudaFuncAttributeMaxDynamicSharedMemorySize, PROJ_DSM);
    cudaFuncSetAttribute(mha_proj_o,     cudaFuncAttributeMaxDynamicSharedMemorySize, PROJ_DSM);
    cudaFuncSetAttribute(mha_scores_mma, cudaFuncAttributeMaxDynamicSharedMemorySize, PROJ_DSM);
    cudaFuncSetAttribute(mha_ctx_mma,    cudaFuncAttributeMaxDynamicSharedMemorySize, CTX_DSM);

    dim3 gqkv(Edim/128, (Sdim*Bdim)/128, 3);        // (8, 32, 3) merged QKV
    mha_proj_qkv<<<gqkv, 256, PROJ_DSM>>>(query, key_, value, Wq, Wk, Wv, bq, bk, bv);

    dim3 gsc(Sdim/128, Sdim/128, Bdim*Hdim);        // (16,16,32)
    mha_scores_mma<<<gsc, 256, PROJ_DSM>>>(bias_matrix, attn);

    mha_rowsum<<<(Bdim*Hdim*Sdim)/256, 256>>>();

    dim3 gctx(Sdim/128, Bdim*Hdim, 2);              // (16,32,2) = 1024 CTAs
    mha_ctx_mma<<<gctx, 256, CTX_DSM>>>(attn);

    dim3 gproj(Edim/128, (Sdim*Bdim)/128);          // (8, 32)
    mha_proj_o<<<gproj, 256, PROJ_DSM>>>(Wo, bo, out);
}

// round 14
// speedup vs baseline: 1.0635x; 1.0277x over previous
#include <cuda_runtime.h>
#include <cuda_bf16.h>
#include <cstdint>

#define Sdim 2048
#define Bdim 2
#define Edim 1024
#define Hdim 16
#define Ddim 64
#define APAD 40   // proj/scores bf16 tile row pad (80B stride)
#define TPAD 72   // ctx tile row pad, 64-wide chunks (144B stride, conflict-free)
#define SP   132  // fp32 staging pad (proj/scores)
#define CP   68   // fp32 staging pad (ctx)

typedef uint32_t u32;

// scratch: static device arrays (allocation-free rule)
__device__ float g_Q[Bdim*Hdim*Sdim*Ddim];     // [B,H,S,D]
__device__ float g_K[Bdim*Hdim*Sdim*Ddim];     // [B,H,S,D]
__device__ float g_V[Bdim*Hdim*Sdim*Ddim];     // [B,H,S,D]
__device__ float g_ctx[Bdim*Sdim*Edim];        // [B,S,E]
__device__ float g_psum[Bdim*Hdim*Sdim*16];    // per-(row, ktile) exp partial sums
__device__ float g_inv[Bdim*Hdim*Sdim];        // 1/rowsum

__device__ __forceinline__ u32 smem_u32(const void* p){
    u32 a;
    asm("{ .reg .u64 t; cvta.to.shared.u64 t, %1; cvt.u32.u64 %0, t; }" : "=r"(a) : "l"(p));
    return a;
}
__device__ __forceinline__ void ldsm4(u32 r[4], u32 addr){
    asm volatile("ldmatrix.sync.aligned.m8n8.x4.shared.b16 {%0,%1,%2,%3}, [%4];"
        : "=r"(r[0]),"=r"(r[1]),"=r"(r[2]),"=r"(r[3]) : "r"(addr));
}
__device__ __forceinline__ void ldsm2t(u32 r[2], u32 addr){
    asm volatile("ldmatrix.sync.aligned.m8n8.x2.trans.shared.b16 {%0,%1}, [%2];"
        : "=r"(r[0]),"=r"(r[1]) : "r"(addr));
}
__device__ __forceinline__ void mma16816(float c[4], const u32 a[4], const u32 b[2]){
    asm volatile("mma.sync.aligned.m16n8k16.row.col.f32.bf16.bf16.f32 "
        "{%0,%1,%2,%3}, {%4,%5,%6,%7}, {%8,%9}, {%0,%1,%2,%3};"
        : "+f"(c[0]),"+f"(c[1]),"+f"(c[2]),"+f"(c[3])
        : "r"(a[0]),"r"(a[1]),"r"(a[2]),"r"(a[3]), "r"(b[0]),"r"(b[1]));
}

// 8 consecutive floats -> 16B hi-bf16 uint4 + 16B lo-bf16 uint4
__device__ __forceinline__ void split8(float4 a, float4 b, uint4& hi, uint4& lo){
    __nv_bfloat16 h0=__float2bfloat16(a.x), h1=__float2bfloat16(a.y),
                  h2=__float2bfloat16(a.z), h3=__float2bfloat16(a.w),
                  h4=__float2bfloat16(b.x), h5=__float2bfloat16(b.y),
                  h6=__float2bfloat16(b.z), h7=__float2bfloat16(b.w);
    __nv_bfloat162 p0=__halves2bfloat162(h0,h1), p1=__halves2bfloat162(h2,h3),
                   p2=__halves2bfloat162(h4,h5), p3=__halves2bfloat162(h6,h7);
    hi = make_uint4(*(u32*)&p0, *(u32*)&p1, *(u32*)&p2, *(u32*)&p3);
    __nv_bfloat162 q0=__floats2bfloat162_rn(a.x-__bfloat162float(h0), a.y-__bfloat162float(h1));
    __nv_bfloat162 q1=__floats2bfloat162_rn(a.z-__bfloat162float(h2), a.w-__bfloat162float(h3));
    __nv_bfloat162 q2=__floats2bfloat162_rn(b.x-__bfloat162float(h4), b.y-__bfloat162float(h5));
    __nv_bfloat162 q3=__floats2bfloat162_rn(b.z-__bfloat162float(h6), b.w-__bfloat162float(h7));
    lo = make_uint4(*(u32*)&q0, *(u32*)&q1, *(u32*)&q2, *(u32*)&q3);
}

#define PROJ_DSM (128*SP*4)
// ctx: Ah/Al 128*TPAD bf16 (18432B ea) + Vh/Vl 64*TPAD bf16 (9216B ea) = 55296B
#define CTX_DSM  (2*(128*TPAD*2) + 2*(64*TPAD*2))

// GEMM compute for one 16-wide K slab (4x2 warps, 8 nf), B pairs via ldsm4.
#define GEMM_COMPUTE_128(KS, sAh, sAl, sBh, sBl)                               \
    do {                                                                       \
        u32 ah0[4], ah1[4], al0[4], al1[4];                                    \
        u32 aoff0 = (sAh) + (u32)((wm      + a_r)*APAD + (KS) + a_c) * 2;      \
        u32 aoff1 = (sAh) + (u32)((wm + 16 + a_r)*APAD + (KS) + a_c) * 2;      \
        u32 loff0 = (sAl) + (u32)((wm      + a_r)*APAD + (KS) + a_c) * 2;      \
        u32 loff1 = (sAl) + (u32)((wm + 16 + a_r)*APAD + (KS) + a_c) * 2;      \
        ldsm4(ah0, aoff0); ldsm4(ah1, aoff1);                                  \
        ldsm4(al0, loff0); ldsm4(al1, loff1);                                  \
        _Pragma("unroll")                                                      \
        for (int nf = 0; nf < 8; nf += 2) {                                    \
            u32 bo = (u32)((wn + nf*8 + b_pn + b_pr)*APAD + (KS) + b_pc) * 2;  \
            u32 bh4[4], bl4[4];                                                \
            ldsm4(bh4, (sBh) + bo); ldsm4(bl4, (sBl) + bo);                    \
            mma16816(acc[nf],     ah0, bh4);                                   \
            mma16816(acc[nf],     ah0, bl4);                                   \
            mma16816(acc[nf],     al0, bh4);                                   \
            mma16816(acc[8+nf],   ah1, bh4);                                   \
            mma16816(acc[8+nf],   ah1, bl4);                                   \
            mma16816(acc[8+nf],   al1, bh4);                                   \
            mma16816(acc[nf+1],   ah0, bh4+2);                                 \
            mma16816(acc[nf+1],   ah0, bl4+2);                                 \
            mma16816(acc[nf+1],   al0, bh4+2);                                 \
            mma16816(acc[8+nf+1], ah1, bh4+2);                                 \
            mma16816(acc[8+nf+1], ah1, bl4+2);                                 \
            mma16816(acc[8+nf+1], al1, bh4+2);                                 \
        }                                                                      \
    } while (0)

// ---------------------------------------------------------------------------
// Shared projection core: out[m,f] = sum_e A[m,e]*W[f,e] + bias[f].
// modes 0/1/2: scatter to g_Q/g_K/g_V as [B,H,S,D]; 3: -> outp [S,B,E].
// ---------------------------------------------------------------------------
__device__ __forceinline__ void proj_core(
    const float* __restrict__ A, const float* __restrict__ W,
    const float* __restrict__ bias, float* __restrict__ outp, int mode, char* dsm)
{
    __nv_bfloat16* Ah = (__nv_bfloat16*)dsm;
    __nv_bfloat16* Al = Ah + 128*APAD;
    __nv_bfloat16* Bh = Al + 128*APAD;
    __nv_bfloat16* Bl = Bh + 128*APAD;
    float* stg = (float*)dsm;

    int tid = threadIdx.x, wid = tid >> 5, lane = tid & 31;
    int m0 = blockIdx.y << 7, f0 = blockIdx.x << 7;
    int wm = (wid & 3) << 5, wn = (wid >> 2) << 6;

    u32 sAh = smem_u32(Ah), sAl = smem_u32(Al), sBh = smem_u32(Bh), sBl = smem_u32(Bl);

    int a_r = (lane & 7) + ((lane >> 3) & 1) * 8;
    int a_c = ((lane >> 4) & 1) * 8;
    int b_pr = lane & 7;
    int b_pc = ((lane >> 3) & 1) * 8;
    int b_pn = (lane >> 4) * 8;

    int lr = tid >> 2, lc = (tid & 3) * 8;

    float acc[16][4];
    #pragma unroll
    for (int i = 0; i < 16; i++){ acc[i][0]=0.f; acc[i][1]=0.f; acc[i][2]=0.f; acc[i][3]=0.f; }

    const float* Ap  = A + (size_t)(m0 + lr)*Edim + lc;
    const float* Ap2 = Ap + (size_t)64*Edim;
    const float* Wp  = W + (size_t)(f0 + lr)*Edim + lc;
    const float* Wp2 = Wp + (size_t)64*Edim;

    for (int c = 0; c < 32; c++) {
        float4 a0 = *(const float4*)(Ap  + c*32), a1 = *(const float4*)(Ap  + c*32 + 4);
        float4 a2 = *(const float4*)(Ap2 + c*32), a3 = *(const float4*)(Ap2 + c*32 + 4);
        float4 w0 = *(const float4*)(Wp  + c*32), w1 = *(const float4*)(Wp  + c*32 + 4);
        float4 w2 = *(const float4*)(Wp2 + c*32), w3 = *(const float4*)(Wp2 + c*32 + 4);
        __syncthreads();
        {
            uint4 h,l;
            split8(a0,a1,h,l); *(uint4*)&Ah[lr*APAD+lc]=h;      *(uint4*)&Al[lr*APAD+lc]=l;
            split8(a2,a3,h,l); *(uint4*)&Ah[(lr+64)*APAD+lc]=h; *(uint4*)&Al[(lr+64)*APAD+lc]=l;
            split8(w0,w1,h,l); *(uint4*)&Bh[lr*APAD+lc]=h;      *(uint4*)&Bl[lr*APAD+lc]=l;
            split8(w2,w3,h,l); *(uint4*)&Bh[(lr+64)*APAD+lc]=h; *(uint4*)&Bl[(lr+64)*APAD+lc]=l;
        }
        __syncthreads();
        GEMM_COMPUTE_128(0,  sAh, sAl, sBh, sBl);
        GEMM_COMPUTE_128(16, sAh, sAl, sBh, sBl);
    }

    // ---- staged epilogue ----
    __syncthreads();
    int gr = lane >> 2, ti = lane & 3;
    #pragma unroll
    for (int mf = 0; mf < 2; mf++)
        #pragma unroll
        for (int nf = 0; nf < 8; nf++)
            #pragma unroll
            for (int hh = 0; hh < 2; hh++) {
                int row = wm + mf*16 + gr + hh*8;
                int col = wn + nf*8 + ti*2;
                *(float2*)&stg[row*SP + col] =
                    make_float2(acc[mf*8+nf][hh*2], acc[mf*8+nf][hh*2+1]);
            }
    __syncthreads();

    float4 bz = *(const float4*)&bias[f0 + lane*4];
    #pragma unroll 4
    for (int it = 0; it < 16; it++) {
        int ml = it*8 + wid;
        int m = m0 + ml;
        float4 v = *(float4*)&stg[ml*SP + lane*4];
        v.x += bz.x; v.y += bz.y; v.z += bz.z; v.w += bz.w;
        if (mode < 3) {
            int s = m >> 1, b = m & 1;
            int f = f0 + lane*4, h = f >> 6, d = f & 63;
            float* dst = (mode==0) ? g_Q : (mode==1) ? g_K : g_V;
            *(float4*)&dst[(((size_t)(b*Hdim + h))*Sdim + s)*Ddim + d] = v;
        } else {
            int b = m >> 11, s = m & 2047;
            *(float4*)&outp[((size_t)s*Bdim + b)*Edim + f0 + lane*4] = v;
        }
    }
}

// Merged QKV projection: blockIdx.z selects {query->Q, key->K, value->V}.
__global__ void __launch_bounds__(256, 2)
mha_proj_qkv(const float* __restrict__ q, const float* __restrict__ k,
             const float* __restrict__ v,
             const float* __restrict__ Wq, const float* __restrict__ Wk,
             const float* __restrict__ Wv,
             const float* __restrict__ bq, const float* __restrict__ bk,
             const float* __restrict__ bv)
{
    extern __shared__ __align__(16) char dsm[];
    int z = blockIdx.z;
    const float* A    = (z==0) ? q  : (z==1) ? k  : v;
    const float* W    = (z==0) ? Wq : (z==1) ? Wk : Wv;
    const float* bias = (z==0) ? bq : (z==1) ? bk : bv;
    proj_core(A, W, bias, nullptr, z, dsm);
}

// Output projection (mode 3): A = g_ctx, result -> out [S,B,E].
__global__ void __launch_bounds__(256, 2)
mha_proj_o(const float* __restrict__ Wo, const float* __restrict__ bo,
           float* __restrict__ outp)
{
    extern __shared__ __align__(16) char dsm[];
    proj_core(g_ctx, Wo, bo, outp, 3, dsm);
}

// ---------------------------------------------------------------------------
// Scores+exp: attn[bh,q,k] = exp(0.125*(Q·K) + bias[q,k]) (unnormalized),
// plus per-(row, ktile) partial sums into g_psum. 128x128 tile, K=64.
// ---------------------------------------------------------------------------
__global__ void __launch_bounds__(256, 2)
mha_scores_mma(const float* __restrict__ bias, float* __restrict__ attn)
{
    extern __shared__ __align__(16) char dsm[];
    __nv_bfloat16* Ah = (__nv_bfloat16*)dsm;
    __nv_bfloat16* Al = Ah + 128*APAD;
    __nv_bfloat16* Bh = Al + 128*APAD;
    __nv_bfloat16* Bl = Bh + 128*APAD;
    float* stg = (float*)dsm;

    int tid = threadIdx.x, wid = tid >> 5, lane = tid & 31;
    int k0 = blockIdx.x << 7, q0 = blockIdx.y << 7, bh = blockIdx.z;
    int wm = (wid & 3) << 5, wn = (wid >> 2) << 6;
    const float* Qg = g_Q + ((size_t)bh*Sdim + q0)*Ddim;
    const float* Kg = g_K + ((size_t)bh*Sdim + k0)*Ddim;

    u32 sAh = smem_u32(Ah), sAl = smem_u32(Al), sBh = smem_u32(Bh), sBl = smem_u32(Bl);
    int a_r = (lane & 7) + ((lane >> 3) & 1) * 8;
    int a_c = ((lane >> 4) & 1) * 8;
    int b_pr = lane & 7;
    int b_pc = ((lane >> 3) & 1) * 8;
    int b_pn = (lane >> 4) * 8;

    int lr = tid >> 2, lc = (tid & 3) * 8;
    const float* Qp  = Qg + (size_t)lr*Ddim + lc;
    const float* Qp2 = Qp + (size_t)64*Ddim;
    const float* Kp  = Kg + (size_t)lr*Ddim + lc;
    const float* Kp2 = Kp + (size_t)64*Ddim;

    float acc[16][4];
    #pragma unroll
    for (int i = 0; i < 16; i++){ acc[i][0]=0.f; acc[i][1]=0.f; acc[i][2]=0.f; acc[i][3]=0.f; }

    for (int c = 0; c < 2; c++) {
        float4 a0 = *(const float4*)(Qp  + c*32), a1 = *(const float4*)(Qp  + c*32 + 4);
        float4 a2 = *(const float4*)(Qp2 + c*32), a3 = *(const float4*)(Qp2 + c*32 + 4);
        float4 w0 = *(const float4*)(Kp  + c*32), w1 = *(const float4*)(Kp  + c*32 + 4);
        float4 w2 = *(const float4*)(Kp2 + c*32), w3 = *(const float4*)(Kp2 + c*32 + 4);
        __syncthreads();
        {
            uint4 h,l;
            split8(a0,a1,h,l); *(uint4*)&Ah[lr*APAD+lc]=h;      *(uint4*)&Al[lr*APAD+lc]=l;
            split8(a2,a3,h,l); *(uint4*)&Ah[(lr+64)*APAD+lc]=h; *(uint4*)&Al[(lr+64)*APAD+lc]=l;
            split8(w0,w1,h,l); *(uint4*)&Bh[lr*APAD+lc]=h;      *(uint4*)&Bl[lr*APAD+lc]=l;
            split8(w2,w3,h,l); *(uint4*)&Bh[(lr+64)*APAD+lc]=h; *(uint4*)&Bl[(lr+64)*APAD+lc]=l;
        }
        __syncthreads();
        GEMM_COMPUTE_128(0,  sAh, sAl, sBh, sBl);
        GEMM_COMPUTE_128(16, sAh, sAl, sBh, sBl);
    }

    // ---- staged epilogue: exp + partial row sums ----
    __syncthreads();
    int gr = lane >> 2, ti = lane & 3;
    #pragma unroll
    for (int mf = 0; mf < 2; mf++)
        #pragma unroll
        for (int nf = 0; nf < 8; nf++)
            #pragma unroll
            for (int hh = 0; hh < 2; hh++) {
                int row = wm + mf*16 + gr + hh*8;
                int col = wn + nf*8 + ti*2;
                *(float2*)&stg[row*SP + col] =
                    make_float2(acc[mf*8+nf][hh*2], acc[mf*8+nf][hh*2+1]);
            }
    __syncthreads();

    #pragma unroll 4
    for (int it = 0; it < 16; it++) {
        int r = it*8 + wid;
        float4 v = *(float4*)&stg[r*SP + lane*4];
        float4 bz = *(const float4*)&bias[(size_t)(q0+r)*Sdim + k0 + lane*4];
        float4 e;
        e.x = __expf(v.x*0.125f + bz.x);
        e.y = __expf(v.y*0.125f + bz.y);
        e.z = __expf(v.z*0.125f + bz.z);
        e.w = __expf(v.w*0.125f + bz.w);
        *(float4*)&attn[((size_t)bh*Sdim + q0 + r)*Sdim + k0 + lane*4] = e;
        float s4 = (e.x + e.y) + (e.z + e.w);
        #pragma unroll
        for (int o=16;o>0;o>>=1) s4 += __shfl_xor_sync(0xffffffffu, s4, o);
        if (lane == 0)
            g_psum[((size_t)bh*Sdim + q0 + r)*16 + (k0 >> 7)] = s4;
    }
}

// ---------------------------------------------------------------------------
// Row-sum reduce: g_inv[row] = 1 / sum(g_psum[row][0..15]).
// ---------------------------------------------------------------------------
__global__ void __launch_bounds__(256)
mha_rowsum(void)
{
    int row = blockIdx.x*256 + threadIdx.x;
    const float4* p = (const float4*)&g_psum[(size_t)row*16];
    float4 a = p[0], b = p[1], c = p[2], d = p[3];
    float s = ((a.x+a.y)+(a.z+a.w)) + ((b.x+b.y)+(b.z+b.w))
            + ((c.x+c.y)+(c.z+c.w)) + ((d.x+d.y)+(d.z+d.w));
    g_inv[row] = 1.0f / s;
}

// ---------------------------------------------------------------------------
// Context: normalizes attn in place (each CTA owns a 128-row strip exclusively),
// and ctx[b,s,h*64+d] = sum_k attn_norm[bh,s,k] * V[bh,k,d].
// 128(q) x 64(d) tile, K=2048 in 32 chunks of 64 (2 sub-loads per chunk).
// ---------------------------------------------------------------------------
__global__ void __launch_bounds__(256, 2)
mha_ctx_mma(float* __restrict__ attn)
{
    extern __shared__ __align__(16) char dsm[];
    __nv_bfloat16* Ah = (__nv_bfloat16*)dsm;          // 128 x TPAD
    __nv_bfloat16* Al = Ah + 128*TPAD;
    __nv_bfloat16* Vh = Al + 128*TPAD;                // 64 x TPAD
    __nv_bfloat16* Vl = Vh + 64*TPAD;
    float* stg = (float*)dsm;

    int tid = threadIdx.x, wid = tid >> 5, lane = tid & 31;
    int q0 = blockIdx.x << 7, bh = blockIdx.y;
    int b = bh >> 4, h = bh & 15;
    int wm = (wid & 3) << 5, wn = (wid >> 2) << 5;
    float* Ag = attn + ((size_t)bh*Sdim + q0)*Sdim;
    const float* Vg = g_V + (size_t)bh*Sdim*Ddim;

    u32 sAh = smem_u32(Ah), sAl = smem_u32(Al), sVh = smem_u32(Vh), sVl = smem_u32(Vl);
    int a_r = (lane & 7) + ((lane >> 3) & 1) * 8;
    int a_c = ((lane >> 4) & 1) * 8;

    int lr = tid >> 2, lc = (tid & 3) * 8;       // attn loads: 64 rows x 32 per pass
    int vr = tid >> 3, vc = (tid & 7) * 8;       // V loads: 32 rows x 64 per pass
    float* Ap  = Ag + (size_t)lr*Sdim + lc;
    float* Ap2 = Ap + (size_t)64*Sdim;
    const float* Vp = Vg + (size_t)vr*Ddim + vc;

    float invA  = g_inv[(size_t)bh*Sdim + q0 + lr];
    float invA2 = g_inv[(size_t)bh*Sdim + q0 + lr + 64];

    float acc[8][4];
    #pragma unroll
    for (int i = 0; i < 8; i++){ acc[i][0]=0.f; acc[i][1]=0.f; acc[i][2]=0.f; acc[i][3]=0.f; }

    for (int c = 0; c < 32; c++) {
        int k0c = c*64;
        // sub-chunk 0 loads (cols k0c..k0c+31)
        float4 a0 = *(const float4*)(Ap  + k0c), a1 = *(const float4*)(Ap  + k0c + 4);
        float4 a2 = *(const float4*)(Ap2 + k0c), a3 = *(const float4*)(Ap2 + k0c + 4);
        float4 v0 = *(const float4*)(Vp + (size_t)k0c*Ddim);
        float4 v1 = *(const float4*)(Vp + (size_t)k0c*Ddim + 4);
        a0.x*=invA;  a0.y*=invA;  a0.z*=invA;  a0.w*=invA;
        a1.x*=invA;  a1.y*=invA;  a1.z*=invA;  a1.w*=invA;
        a2.x*=invA2; a2.y*=invA2; a2.z*=invA2; a2.w*=invA2;
        a3.x*=invA2; a3.y*=invA2; a3.z*=invA2; a3.w*=invA2;
        *(float4*)(Ap  + k0c)     = a0;
        *(float4*)(Ap  + k0c + 4) = a1;
        *(float4*)(Ap2 + k0c)     = a2;
        *(float4*)(Ap2 + k0c + 4) = a3;
        __syncthreads();
        {
            uint4 h4,l4;
            split8(a0,a1,h4,l4); *(uint4*)&Ah[lr*TPAD+lc]=h4;      *(uint4*)&Al[lr*TPAD+lc]=l4;
            split8(a2,a3,h4,l4); *(uint4*)&Ah[(lr+64)*TPAD+lc]=h4; *(uint4*)&Al[(lr+64)*TPAD+lc]=l4;
            split8(v0,v1,h4,l4); *(uint4*)&Vh[vr*TPAD+vc]=h4;      *(uint4*)&Vl[vr*TPAD+vc]=l4;
        }
        // sub-chunk 1 loads (cols k0c+32..k0c+63) — latency overlaps STS above
        {
            float4 b0 = *(const float4*)(Ap  + k0c + 32), b1 = *(const float4*)(Ap  + k0c + 36);
            float4 b2 = *(const float4*)(Ap2 + k0c + 32), b3 = *(const float4*)(Ap2 + k0c + 36);
            float4 w0 = *(const float4*)(Vp + (size_t)(k0c + 32)*Ddim);
            float4 w1 = *(const float4*)(Vp + (size_t)(k0c + 32)*Ddim + 4);
            b0.x*=invA;  b0.y*=invA;  b0.z*=invA;  b0.w*=invA;
            b1.x*=invA;  b1.y*=invA;  b1.z*=invA;  b1.w*=invA;
            b2.x*=invA2; b2.y*=invA2; b2.z*=invA2; b2.w*=invA2;
            b3.x*=invA2; b3.y*=invA2; b3.z*=invA2; b3.w*=invA2;
            *(float4*)(Ap  + k0c + 32) = b0;
            *(float4*)(Ap  + k0c + 36) = b1;
            *(float4*)(Ap2 + k0c + 32) = b2;
            *(float4*)(Ap2 + k0c + 36) = b3;
            uint4 h4,l4;
            split8(b0,b1,h4,l4);
            *(uint4*)&Ah[lr*TPAD+32+lc]=h4;      *(uint4*)&Al[lr*TPAD+32+lc]=l4;
            split8(b2,b3,h4,l4);
            *(uint4*)&Ah[(lr+64)*TPAD+32+lc]=h4; *(uint4*)&Al[(lr+64)*TPAD+32+lc]=l4;
            split8(w0,w1,h4,l4);
            *(uint4*)&Vh[(vr+32)*TPAD+vc]=h4;    *(uint4*)&Vl[(vr+32)*TPAD+vc]=l4;
        }
        __syncthreads();
        #pragma unroll
        for (int ks = 0; ks < 64; ks += 16) {
            u32 ah0[4], ah1[4], al0[4], al1[4];
            u32 aoff0 = (u32)((wm      + a_r)*TPAD + ks + a_c) * 2;
            u32 aoff1 = (u32)((wm + 16 + a_r)*TPAD + ks + a_c) * 2;
            ldsm4(ah0, sAh + aoff0); ldsm4(ah1, sAh + aoff1);
            ldsm4(al0, sAl + aoff0); ldsm4(al1, sAl + aoff1);
            #pragma unroll
            for (int nf = 0; nf < 4; nf++) {
                u32 bo = (u32)((ks + (lane & 15))*TPAD + wn + nf*8) * 2;
                u32 bhf[2], blf[2];
                ldsm2t(bhf, sVh + bo); ldsm2t(blf, sVl + bo);
                mma16816(acc[nf],   ah0, bhf);
                mma16816(acc[nf],   ah0, blf);
                mma16816(acc[nf],   al0, bhf);
                mma16816(acc[4+nf], ah1, bhf);
                mma16816(acc[4+nf], ah1, blf);
                mma16816(acc[4+nf], al1, bhf);
            }
        }
    }

    // ---- staged epilogue ----
    __syncthreads();
    int gr = lane >> 2, ti = lane & 3;
    #pragma unroll
    for (int mf = 0; mf < 2; mf++)
        #pragma unroll
        for (int nf = 0; nf < 4; nf++)
            #pragma unroll
            for (int hh = 0; hh < 2; hh++) {
                int row = wm + mf*16 + gr + hh*8;
                int col = wn + nf*8 + ti*2;
                *(float2*)&stg[row*CP + col] =
                    make_float2(acc[mf*4+nf][hh*2], acc[mf*4+nf][hh*2+1]);
            }
    __syncthreads();

    #pragma unroll 4
    for (int it = 0; it < 8; it++) {
        int r = it*16 + wid*2 + (lane >> 4);
        float4 v = *(float4*)&stg[r*CP + (lane & 15)*4];
        int s = q0 + r;
        *(float4*)&g_ctx[((size_t)b*Sdim + s)*Edim + h*64 + (lane & 15)*4] = v;
    }
}

extern "C" void kernel_launch(void* const* d_in, const int* in_sizes, int n_in,
                              void* d_out, int out_size) {
    const float* query = (const float*)d_in[0];
    const float* key_  = (const float*)d_in[1];
    const float* value = (const float*)d_in[2];
    const float* Wq = (const float*)d_in[3];
    const float* bq = (const float*)d_in[4];
    const float* Wk = (const float*)d_in[5];
    const float* bk = (const float*)d_in[6];
    const float* Wv = (const float*)d_in[7];
    const float* bv = (const float*)d_in[8];
    const float* Wo = (const float*)d_in[9];
    const float* bo = (const float*)d_in[10];
    const float* bias_matrix = (const float*)d_in[11];

    float* out  = (float*)d_out;                    // [S,B,E]
    float* attn = out + (size_t)Sdim*Bdim*Edim;     // [B,H,S,S]

    cudaFuncSetAttribute(mha_proj_qkv,   cudaFuncAttributeMaxDynamicSharedMemorySize, PROJ_DSM);
    cudaFuncSetAttribute(mha_proj_o,     cudaFuncAttributeMaxDynamicSharedMemorySize, PROJ_DSM);
    cudaFuncSetAttribute(mha_scores_mma, cudaFuncAttributeMaxDynamicSharedMemorySize, PROJ_DSM);
    cudaFuncSetAttribute(mha_ctx_mma,    cudaFuncAttributeMaxDynamicSharedMemorySize, CTX_DSM);

    dim3 gqkv(Edim/128, (Sdim*Bdim)/128, 3);        // (8, 32, 3) merged QKV
    mha_proj_qkv<<<gqkv, 256, PROJ_DSM>>>(query, key_, value, Wq, Wk, Wv, bq, bk, bv);

    dim3 gsc(Sdim/128, Sdim/128, Bdim*Hdim);        // (16,16,32)
    mha_scores_mma<<<gsc, 256, PROJ_DSM>>>(bias_matrix, attn);

    mha_rowsum<<<(Bdim*Hdim*Sdim)/256, 256>>>();

    dim3 gctx(Sdim/128, Bdim*Hdim);                 // (16,32)
    mha_ctx_mma<<<gctx, 256, CTX_DSM>>>(attn);

    dim3 gproj(Edim/128, (Sdim*Bdim)/128);          // (8, 32)
    mha_proj_o<<<gproj, 256, PROJ_DSM>>>(Wo, bo, out);
}